// round 1
// baseline (speedup 1.0000x reference)
#include <cuda_runtime.h>
#include <math_constants.h>
#include <math.h>

#define NN 50000
#define EE 800000
#define BB 64
#define DD 128
#define LL 4
#define HRD 640      /* D*(L+1) */
#define NOUT 10
#define BN_EPS 1e-5

// ---------------- scratch (device globals; no allocation allowed) ----------
__device__ __align__(16) float  g_hr[(size_t)NN * HRD];   // [x | h1 | h2 | h3 | h4]
__device__ __align__(16) float  g_pooled[NN * DD];
__device__ __align__(16) float  g_z1[NN * DD];
__device__ __align__(16) float  g_z2[NN * DD];
__device__ double g_sum[DD];
__device__ double g_sumsq[DD];
__device__ __align__(16) float  g_bn_a[DD];
__device__ __align__(16) float  g_bn_c[DD];
__device__ float  g_scores[NN];
__device__ float  g_expv[NN];
__device__ float  g_smax[BB];
__device__ float  g_denom[BB];
__device__ __align__(16) float  g_gemb[BB * HRD];

// ---------------- packed f32x2 helpers (Blackwell) --------------------------
__device__ __forceinline__ void ffma2(unsigned long long& acc,
                                      unsigned long long a,
                                      unsigned long long b) {
    asm("fma.rn.f32x2 %0, %1, %2, %0;" : "+l"(acc) : "l"(a), "l"(b));
}
__device__ __forceinline__ unsigned long long splat2(float a) {
    unsigned long long r;
    asm("mov.b64 %0, {%1, %1};" : "=l"(r) : "f"(a));
    return r;
}
__device__ __forceinline__ float2 unpack2(unsigned long long v) {
    float2 r;
    asm("mov.b64 {%0, %1}, %2;" : "=f"(r.x), "=f"(r.y) : "l"(v));
    return r;
}

__device__ __forceinline__ void atomicMaxF(float* addr, float val) {
    int old = __float_as_int(*addr);
    while (__int_as_float(old) < val) {
        int assumed = old;
        old = atomicCAS((int*)addr, assumed, __float_as_int(val));
        if (old == assumed) break;
    }
}

// ---------------- elementwise kernels ---------------------------------------
__global__ void copy_x_kernel(const float* __restrict__ x) {
    int idx = blockIdx.x * blockDim.x + threadIdx.x;
    if (idx >= NN * 32) return;
    int i = idx >> 5, c = idx & 31;
    reinterpret_cast<float4*>(g_hr + (size_t)i * HRD)[c] =
        reinterpret_cast<const float4*>(x + (size_t)i * DD)[c];
}

__global__ void init_pooled_kernel(int l, const float* __restrict__ eps) {
    int idx = blockIdx.x * blockDim.x + threadIdx.x;
    if (idx >= NN * 32) return;
    int i = idx >> 5, c = idx & 31;
    float s = 1.0f + eps[l];
    float4 v = reinterpret_cast<const float4*>(g_hr + (size_t)i * HRD + l * DD)[c];
    float4 o = make_float4(s * v.x, s * v.y, s * v.z, s * v.w);
    reinterpret_cast<float4*>(g_pooled + (size_t)i * DD)[c] = o;
}

__global__ void edge_scatter_kernel(int l, const int* __restrict__ src,
                                    const int* __restrict__ dst) {
    int idx = blockIdx.x * blockDim.x + threadIdx.x;
    if (idx >= EE * 32) return;
    int e = idx >> 5, lane = idx & 31;
    int s = src[e], d = dst[e];
    float4 v = reinterpret_cast<const float4*>(g_hr + (size_t)s * HRD + l * DD)[lane];
    float* p = g_pooled + (size_t)d * DD + lane * 4;
    atomicAdd(p + 0, v.x);
    atomicAdd(p + 1, v.y);
    atomicAdd(p + 2, v.z);
    atomicAdd(p + 3, v.w);
}

// h_{l+1} = relu(a*z2 + c), written into hr slab
__global__ void apply_h_kernel(int l) {
    int idx = blockIdx.x * blockDim.x + threadIdx.x;
    if (idx >= NN * 32) return;
    int i = idx >> 5, c = idx & 31;
    float4 z = reinterpret_cast<const float4*>(g_z2 + (size_t)i * DD)[c];
    float4 a = reinterpret_cast<const float4*>(g_bn_a)[c];
    float4 b = reinterpret_cast<const float4*>(g_bn_c)[c];
    float4 o;
    o.x = fmaxf(fmaf(a.x, z.x, b.x), 0.f);
    o.y = fmaxf(fmaf(a.y, z.y, b.y), 0.f);
    o.z = fmaxf(fmaf(a.z, z.z, b.z), 0.f);
    o.w = fmaxf(fmaf(a.w, z.w, b.w), 0.f);
    reinterpret_cast<float4*>(g_hr + (size_t)i * HRD + (size_t)(l + 1) * DD)[c] = o;
}

// ---------------- GEMM: C[N,128] = (opt transform)(A)[N,128] @ W[128,128] + b
// SECOND=false: A=g_pooled, C=g_z1, no input transform
// SECOND=true : A=g_z1 with y=relu(bn_a*x+bn_c), C=g_z2
// Always accumulates column sum / sumsq (double) of C into g_sum/g_sumsq.
#define GEMM_SMEM (DD * DD * 4 + 64 * DD * 4 + 2 * DD * 8)

template <bool SECOND>
__global__ void __launch_bounds__(128) gemm128_kernel(const float* __restrict__ W,
                                                      const float* __restrict__ bias) {
    extern __shared__ float smem[];
    float* Wsh = smem;                       // 128x128
    float* Ash = smem + DD * DD;             // 64x128
    double* redS = reinterpret_cast<double*>(smem + DD * DD + 64 * DD);
    double* redQ = redS + DD;

    const float* A = SECOND ? g_z1 : g_pooled;
    float* C       = SECOND ? g_z2 : g_z1;

    int tid = threadIdx.x;
    redS[tid] = 0.0;
    redQ[tid] = 0.0;

    // load W (16384 floats)
    {
        const float4* Wg = reinterpret_cast<const float4*>(W);
        float4* Ws = reinterpret_cast<float4*>(Wsh);
#pragma unroll
        for (int i = 0; i < 32; i++) Ws[tid + i * 128] = Wg[tid + i * 128];
    }
    // load A tile (64 rows), applying BN-affine+ReLU for the second GEMM
    int row0 = blockIdx.x * 64;
    {
        float4* As = reinterpret_cast<float4*>(Ash);
#pragma unroll
        for (int ii = 0; ii < 16; ii++) {
            int i = tid + ii * 128;
            int r = i >> 5, c4 = i & 31;
            int row = row0 + r;
            float4 v = make_float4(0.f, 0.f, 0.f, 0.f);
            if (row < NN)
                v = *reinterpret_cast<const float4*>(A + (size_t)row * DD + c4 * 4);
            if (SECOND) {
                float4 ba = reinterpret_cast<const float4*>(g_bn_a)[c4];
                float4 bc = reinterpret_cast<const float4*>(g_bn_c)[c4];
                v.x = fmaxf(fmaf(ba.x, v.x, bc.x), 0.f);
                v.y = fmaxf(fmaf(ba.y, v.y, bc.y), 0.f);
                v.z = fmaxf(fmaf(ba.z, v.z, bc.z), 0.f);
                v.w = fmaxf(fmaf(ba.w, v.w, bc.w), 0.f);
            }
            As[i] = v;
        }
    }
    __syncthreads();

    int cg = tid & 15;   // 8 columns:  8*cg .. 8*cg+7
    int rg = tid >> 4;   // 8 rows:     rg*8 .. rg*8+7
    const float* arow = Ash + rg * 8 * DD;

    unsigned long long acc[8][4];
#pragma unroll
    for (int r = 0; r < 8; r++)
#pragma unroll
        for (int p = 0; p < 4; p++) acc[r][p] = 0ull;

#pragma unroll 4
    for (int k = 0; k < DD; k++) {
        const ulonglong2* wp =
            reinterpret_cast<const ulonglong2*>(Wsh + k * DD + cg * 8);
        ulonglong2 w01 = wp[0];
        ulonglong2 w23 = wp[1];
#pragma unroll
        for (int r = 0; r < 8; r++) {
            unsigned long long a2 = splat2(arow[r * DD + k]);
            ffma2(acc[r][0], a2, w01.x);
            ffma2(acc[r][1], a2, w01.y);
            ffma2(acc[r][2], a2, w23.x);
            ffma2(acc[r][3], a2, w23.y);
        }
    }

    float bs[8];
#pragma unroll
    for (int j = 0; j < 8; j++) bs[j] = bias[cg * 8 + j];

    float cs[8], cq[8];
#pragma unroll
    for (int j = 0; j < 8; j++) { cs[j] = 0.f; cq[j] = 0.f; }

#pragma unroll
    for (int r = 0; r < 8; r++) {
        int row = row0 + rg * 8 + r;
        if (row >= NN) continue;
        float o[8];
#pragma unroll
        for (int p = 0; p < 4; p++) {
            float2 u = unpack2(acc[r][p]);
            o[2 * p]     = u.x + bs[2 * p];
            o[2 * p + 1] = u.y + bs[2 * p + 1];
        }
        float4* cp = reinterpret_cast<float4*>(C + (size_t)row * DD + cg * 8);
        cp[0] = make_float4(o[0], o[1], o[2], o[3]);
        cp[1] = make_float4(o[4], o[5], o[6], o[7]);
#pragma unroll
        for (int j = 0; j < 8; j++) {
            cs[j] += o[j];
            cq[j] += o[j] * o[j];
        }
    }
#pragma unroll
    for (int j = 0; j < 8; j++) {
        atomicAdd(&redS[cg * 8 + j], (double)cs[j]);
        atomicAdd(&redQ[cg * 8 + j], (double)cq[j]);
    }
    __syncthreads();
    atomicAdd(&g_sum[tid], redS[tid]);
    atomicAdd(&g_sumsq[tid], redQ[tid]);
}

// turn (sum, sumsq, gamma, beta) into affine (a, c); reset accumulators
__global__ void finalize_bn_kernel(const float* __restrict__ g,
                                   const float* __restrict__ b) {
    int j = threadIdx.x;
    double m = g_sum[j] / (double)NN;
    double v = g_sumsq[j] / (double)NN - m * m;
    double a = (double)g[j] / sqrt(v + (double)BN_EPS);
    g_bn_a[j] = (float)a;
    g_bn_c[j] = (float)((double)b[j] - m * a);
    g_sum[j] = 0.0;
    g_sumsq[j] = 0.0;
}

// ---------------- attention pooling + head ----------------------------------
__global__ void scores_kernel(const float* __restrict__ aw,
                              const float* __restrict__ ab) {
    int t = blockIdx.x * blockDim.x + threadIdx.x;
    int i = t >> 5, lane = t & 31;
    if (i >= NN) return;
    const float4* row = reinterpret_cast<const float4*>(g_hr + (size_t)i * HRD);
    const float4* w4 = reinterpret_cast<const float4*>(aw);
    float acc = 0.f;
#pragma unroll
    for (int j = lane; j < HRD / 4; j += 32) {
        float4 r = row[j], w = w4[j];
        acc += r.x * w.x + r.y * w.y + r.z * w.z + r.w * w.w;
    }
#pragma unroll
    for (int off = 16; off; off >>= 1) acc += __shfl_down_sync(0xffffffffu, acc, off);
    if (lane == 0) g_scores[i] = acc + ab[0];
}

__global__ void init_att_kernel() {
    int idx = blockIdx.x * blockDim.x + threadIdx.x;
    if (idx < BB * HRD) g_gemb[idx] = 0.f;
    if (idx < BB) {
        g_smax[idx] = -CUDART_INF_F;
        g_denom[idx] = 0.f;
    }
}

__global__ void segmax_kernel(const int* __restrict__ gid) {
    int i = blockIdx.x * blockDim.x + threadIdx.x;
    if (i >= NN) return;
    atomicMaxF(&g_smax[gid[i]], g_scores[i]);
}

__global__ void expdenom_kernel(const int* __restrict__ gid) {
    int i = blockIdx.x * blockDim.x + threadIdx.x;
    if (i >= NN) return;
    int g = gid[i];
    float e = expf(g_scores[i] - g_smax[g]);
    g_expv[i] = e;
    atomicAdd(&g_denom[g], e);
}

__global__ void gemb_kernel(const int* __restrict__ gid) {
    int idx = blockIdx.x * blockDim.x + threadIdx.x;
    if (idx >= NN * (HRD / 4)) return;
    int i = idx / (HRD / 4);
    int c = idx - i * (HRD / 4);
    int g = gid[i];
    float coef = g_expv[i] / g_denom[g];
    float4 v = reinterpret_cast<const float4*>(g_hr + (size_t)i * HRD)[c];
    float* p = g_gemb + (size_t)g * HRD + c * 4;
    atomicAdd(p + 0, coef * v.x);
    atomicAdd(p + 1, coef * v.y);
    atomicAdd(p + 2, coef * v.z);
    atomicAdd(p + 3, coef * v.w);
}

__global__ void final_kernel(const float* __restrict__ pi,
                             const float* __restrict__ pi_w,
                             const float* __restrict__ pi_b,
                             const float* __restrict__ out_w,
                             const float* __restrict__ out_b,
                             float* __restrict__ out) {
    __shared__ float pie[16];
    int b = blockIdx.x, tid = threadIdx.x;
    if (tid < 16) {
        float a = pi_b[tid];
#pragma unroll
        for (int k = 0; k < 25; k++) a = fmaf(pi[b * 25 + k], pi_w[k * 16 + tid], a);
        pie[tid] = fmaxf(a, 0.f);
    }
    __syncthreads();
    int o = tid >> 5, lane = tid & 31;
    float acc = 0.f;
    const float* ge = g_gemb + (size_t)b * HRD;
    for (int j = lane; j < HRD; j += 32) acc = fmaf(ge[j], out_w[j * NOUT + o], acc);
    if (lane < 16) acc = fmaf(pie[lane], out_w[(HRD + lane) * NOUT + o], acc);
#pragma unroll
    for (int off = 16; off; off >>= 1) acc += __shfl_down_sync(0xffffffffu, acc, off);
    if (lane == 0) out[b * NOUT + o] = acc + out_b[o];
}

// ---------------- launch -----------------------------------------------------
extern "C" void kernel_launch(void* const* d_in, const int* in_sizes, int n_in,
                              void* d_out, int out_size) {
    const float* x    = (const float*)d_in[0];
    const float* pi   = (const float*)d_in[1];
    const float* eps  = (const float*)d_in[2];
    const float* w1   = (const float*)d_in[3];
    const float* b1   = (const float*)d_in[4];
    const float* bng1 = (const float*)d_in[5];
    const float* bnb1 = (const float*)d_in[6];
    const float* w2   = (const float*)d_in[7];
    const float* b2   = (const float*)d_in[8];
    const float* bng  = (const float*)d_in[9];
    const float* bnb  = (const float*)d_in[10];
    const float* aw   = (const float*)d_in[11];
    const float* ab   = (const float*)d_in[12];
    const float* pw   = (const float*)d_in[13];
    const float* pb   = (const float*)d_in[14];
    const float* ow   = (const float*)d_in[15];
    const float* ob   = (const float*)d_in[16];
    const int*   ei   = (const int*)d_in[17];
    const int*   gid  = (const int*)d_in[18];
    const int* src = ei;
    const int* dst = ei + EE;
    float* out = (float*)d_out;

    cudaFuncSetAttribute(gemm128_kernel<false>,
                         cudaFuncAttributeMaxDynamicSharedMemorySize, GEMM_SMEM);
    cudaFuncSetAttribute(gemm128_kernel<true>,
                         cudaFuncAttributeMaxDynamicSharedMemorySize, GEMM_SMEM);

    const int ELT_BLOCKS = (NN * 32 + 255) / 256;          // 6250
    const int EDGE_BLOCKS = (EE * 32 + 255) / 256;         // 100000
    const int GEMM_BLOCKS = (NN + 63) / 64;                // 782

    copy_x_kernel<<<ELT_BLOCKS, 256>>>(x);

    for (int l = 0; l < LL; l++) {
        init_pooled_kernel<<<ELT_BLOCKS, 256>>>(l, eps);
        edge_scatter_kernel<<<EDGE_BLOCKS, 256>>>(l, src, dst);
        gemm128_kernel<false><<<GEMM_BLOCKS, 128, GEMM_SMEM>>>(w1 + (size_t)l * DD * DD,
                                                               b1 + l * DD);
        finalize_bn_kernel<<<1, DD>>>(bng1 + l * DD, bnb1 + l * DD);
        gemm128_kernel<true><<<GEMM_BLOCKS, 128, GEMM_SMEM>>>(w2 + (size_t)l * DD * DD,
                                                              b2 + l * DD);
        finalize_bn_kernel<<<1, DD>>>(bng + l * DD, bnb + l * DD);
        apply_h_kernel<<<ELT_BLOCKS, 256>>>(l);
    }

    scores_kernel<<<ELT_BLOCKS, 256>>>(aw, ab);
    init_att_kernel<<<(BB * HRD + 255) / 256, 256>>>();
    segmax_kernel<<<(NN + 255) / 256, 256>>>(gid);
    expdenom_kernel<<<(NN + 255) / 256, 256>>>(gid);
    gemb_kernel<<<(NN * (HRD / 4) + 255) / 256, 256>>>(gid);
    final_kernel<<<BB, 320>>>(pi, pw, pb, ow, ob, out);
}

// round 2
// speedup vs baseline: 1.4414x; 1.4414x over previous
#include <cuda_runtime.h>
#include <math_constants.h>
#include <math.h>

#define NN 50000
#define EE 800000
#define BB 64
#define DD 128
#define LL 4
#define HRD 640      /* D*(L+1) */
#define NOUT 10
#define BN_EPS 1e-5

#define SCAN_BLOCKS 49   /* 49*1024 >= 50000 */

// ---------------- scratch (device globals; no allocation allowed) ----------
__device__ __align__(16) float  g_hr[(size_t)NN * HRD];   // [x | h1 | h2 | h3 | h4]
__device__ __align__(16) float  g_pooled[NN * DD];
__device__ __align__(16) float  g_z1[NN * DD];
__device__ __align__(16) float  g_z2[NN * DD];
__device__ double g_sum[DD];
__device__ double g_sumsq[DD];
__device__ __align__(16) float  g_bn_a[DD];
__device__ __align__(16) float  g_bn_c[DD];
__device__ float  g_scores[NN];
__device__ float  g_expv[NN];
__device__ float  g_smax[BB];
__device__ float  g_denom[BB];
__device__ __align__(16) float  g_gemb[BB * HRD];
// CSR scratch
__device__ int g_cnt[NN];
__device__ int g_cur[NN];
__device__ int g_rowptr[NN + 1];
__device__ int g_bsum[SCAN_BLOCKS];
__device__ int g_esrc[EE];

// ---------------- packed f32x2 helpers (Blackwell) --------------------------
__device__ __forceinline__ void ffma2(unsigned long long& acc,
                                      unsigned long long a,
                                      unsigned long long b) {
    asm("fma.rn.f32x2 %0, %1, %2, %0;" : "+l"(acc) : "l"(a), "l"(b));
}
__device__ __forceinline__ unsigned long long splat2(float a) {
    unsigned long long r;
    asm("mov.b64 %0, {%1, %1};" : "=l"(r) : "f"(a));
    return r;
}
__device__ __forceinline__ float2 unpack2(unsigned long long v) {
    float2 r;
    asm("mov.b64 {%0, %1}, %2;" : "=f"(r.x), "=f"(r.y) : "l"(v));
    return r;
}

__device__ __forceinline__ void atomicMaxF(float* addr, float val) {
    int old = __float_as_int(*addr);
    while (__int_as_float(old) < val) {
        int assumed = old;
        old = atomicCAS((int*)addr, assumed, __float_as_int(val));
        if (old == assumed) break;
    }
}

// ---------------- CSR construction ------------------------------------------
__global__ void zero_cnt_kernel() {
    int i = blockIdx.x * blockDim.x + threadIdx.x;
    if (i < NN) { g_cnt[i] = 0; g_cur[i] = 0; }
}

__global__ void hist_kernel(const int* __restrict__ dst) {
    int e = blockIdx.x * blockDim.x + threadIdx.x;
    if (e < EE) atomicAdd(&g_cnt[dst[e]], 1);
}

__global__ void scan1_kernel() {
    __shared__ int sh[1024];
    int tid = threadIdx.x;
    int g = blockIdx.x * 1024 + tid;
    int v = (g < NN) ? g_cnt[g] : 0;
    sh[tid] = v;
    __syncthreads();
#pragma unroll
    for (int off = 1; off < 1024; off <<= 1) {
        int t = (tid >= off) ? sh[tid - off] : 0;
        __syncthreads();
        sh[tid] += t;
        __syncthreads();
    }
    if (g < NN) g_rowptr[g] = sh[tid] - v;  // exclusive within block
    if (tid == 1023) g_bsum[blockIdx.x] = sh[1023];
}

__global__ void scan2_kernel() {
    int run = 0;
    for (int i = 0; i < SCAN_BLOCKS; i++) {
        int t = g_bsum[i];
        g_bsum[i] = run;
        run += t;
    }
}

__global__ void scan3_kernel() {
    int tid = threadIdx.x;
    int g = blockIdx.x * 1024 + tid;
    if (g < NN) g_rowptr[g] += g_bsum[blockIdx.x];
    if (g == 0) g_rowptr[NN] = EE;
}

__global__ void scatter_kernel(const int* __restrict__ src,
                               const int* __restrict__ dst) {
    int e = blockIdx.x * blockDim.x + threadIdx.x;
    if (e >= EE) return;
    int d = dst[e];
    int p = g_rowptr[d] + atomicAdd(&g_cur[d], 1);
    g_esrc[p] = src[e];
}

// ---------------- elementwise kernels ---------------------------------------
__global__ void copy_x_kernel(const float* __restrict__ x) {
    int idx = blockIdx.x * blockDim.x + threadIdx.x;
    if (idx >= NN * 32) return;
    int i = idx >> 5, c = idx & 31;
    reinterpret_cast<float4*>(g_hr + (size_t)i * HRD)[c] =
        reinterpret_cast<const float4*>(x + (size_t)i * DD)[c];
}

// pooled[i] = sum_{incoming edges} h[src] + (1+eps)*h[i]   (gather via CSR)
__global__ void aggregate_kernel(int l, const float* __restrict__ eps) {
    int idx = blockIdx.x * blockDim.x + threadIdx.x;
    int i = idx >> 5, lane = idx & 31;
    if (i >= NN) return;
    int beg = g_rowptr[i], end = g_rowptr[i + 1];
    const float* hbase = g_hr + (size_t)l * DD;
    float4 acc = make_float4(0.f, 0.f, 0.f, 0.f);
    int e = beg;
    for (; e + 1 < end; e += 2) {
        int s0 = g_esrc[e], s1 = g_esrc[e + 1];
        float4 v0 = reinterpret_cast<const float4*>(hbase + (size_t)s0 * HRD)[lane];
        float4 v1 = reinterpret_cast<const float4*>(hbase + (size_t)s1 * HRD)[lane];
        acc.x += v0.x + v1.x;
        acc.y += v0.y + v1.y;
        acc.z += v0.z + v1.z;
        acc.w += v0.w + v1.w;
    }
    if (e < end) {
        int s0 = g_esrc[e];
        float4 v0 = reinterpret_cast<const float4*>(hbase + (size_t)s0 * HRD)[lane];
        acc.x += v0.x; acc.y += v0.y; acc.z += v0.z; acc.w += v0.w;
    }
    float sc = 1.0f + eps[l];
    float4 h = reinterpret_cast<const float4*>(hbase + (size_t)i * HRD)[lane];
    acc.x = fmaf(sc, h.x, acc.x);
    acc.y = fmaf(sc, h.y, acc.y);
    acc.z = fmaf(sc, h.z, acc.z);
    acc.w = fmaf(sc, h.w, acc.w);
    reinterpret_cast<float4*>(g_pooled + (size_t)i * DD)[lane] = acc;
}

// h_{l+1} = relu(a*z2 + c), written into hr slab
__global__ void apply_h_kernel(int l) {
    int idx = blockIdx.x * blockDim.x + threadIdx.x;
    if (idx >= NN * 32) return;
    int i = idx >> 5, c = idx & 31;
    float4 z = reinterpret_cast<const float4*>(g_z2 + (size_t)i * DD)[c];
    float4 a = reinterpret_cast<const float4*>(g_bn_a)[c];
    float4 b = reinterpret_cast<const float4*>(g_bn_c)[c];
    float4 o;
    o.x = fmaxf(fmaf(a.x, z.x, b.x), 0.f);
    o.y = fmaxf(fmaf(a.y, z.y, b.y), 0.f);
    o.z = fmaxf(fmaf(a.z, z.z, b.z), 0.f);
    o.w = fmaxf(fmaf(a.w, z.w, b.w), 0.f);
    reinterpret_cast<float4*>(g_hr + (size_t)i * HRD + (size_t)(l + 1) * DD)[c] = o;
}

// ---------------- GEMM: C[N,128] = (opt transform)(A)[N,128] @ W[128,128] + b
// A tile in smem (128 rows); W streamed from global (L1/L2 resident, shared by
// all blocks). Also accumulates column sum/sumsq (double) of C.
#define GEMM_SMEM (128 * DD * 4 + 2 * DD * 8)

template <bool SECOND>
__global__ void __launch_bounds__(256, 2) gemm128_kernel(const float* __restrict__ W,
                                                         const float* __restrict__ bias) {
    extern __shared__ float smem[];
    float* Ash = smem;                                        // 128x128
    double* redS = reinterpret_cast<double*>(smem + 128 * DD);
    double* redQ = redS + DD;

    const float* A = SECOND ? g_z1 : g_pooled;
    float* C       = SECOND ? g_z2 : g_z1;

    int tid = threadIdx.x;
    if (tid < DD) { redS[tid] = 0.0; redQ[tid] = 0.0; }

    int row0 = blockIdx.x * 128;
    {
        float4* As = reinterpret_cast<float4*>(Ash);
#pragma unroll
        for (int ii = 0; ii < 16; ii++) {
            int i = tid + ii * 256;             // float4 index, 0..4095
            int r = i >> 5, c4 = i & 31;
            int row = row0 + r;
            float4 v = make_float4(0.f, 0.f, 0.f, 0.f);
            if (row < NN)
                v = *reinterpret_cast<const float4*>(A + (size_t)row * DD + c4 * 4);
            if (SECOND) {
                float4 ba = reinterpret_cast<const float4*>(g_bn_a)[c4];
                float4 bc = reinterpret_cast<const float4*>(g_bn_c)[c4];
                v.x = fmaxf(fmaf(ba.x, v.x, bc.x), 0.f);
                v.y = fmaxf(fmaf(ba.y, v.y, bc.y), 0.f);
                v.z = fmaxf(fmaf(ba.z, v.z, bc.z), 0.f);
                v.w = fmaxf(fmaf(ba.w, v.w, bc.w), 0.f);
            }
            As[i] = v;
        }
    }
    __syncthreads();

    int cg = tid & 15;   // 8 columns:  8*cg .. 8*cg+7
    int rg = tid >> 4;   // 8 rows:     rg*8 .. rg*8+7
    const float* arow = Ash + rg * 8 * DD;
    const ulonglong2* Wg = reinterpret_cast<const ulonglong2*>(W);

    unsigned long long acc[8][4];
#pragma unroll
    for (int r = 0; r < 8; r++)
#pragma unroll
        for (int p = 0; p < 4; p++) acc[r][p] = 0ull;

#pragma unroll 4
    for (int k = 0; k < DD; k++) {
        ulonglong2 wA = __ldg(&Wg[k * 32 + cg * 2]);
        ulonglong2 wB = __ldg(&Wg[k * 32 + cg * 2 + 1]);
#pragma unroll
        for (int r = 0; r < 8; r++) {
            unsigned long long a2 = splat2(arow[r * DD + k]);
            ffma2(acc[r][0], a2, wA.x);
            ffma2(acc[r][1], a2, wA.y);
            ffma2(acc[r][2], a2, wB.x);
            ffma2(acc[r][3], a2, wB.y);
        }
    }

    float bs[8];
#pragma unroll
    for (int j = 0; j < 8; j++) bs[j] = bias[cg * 8 + j];

    float cs[8], cq[8];
#pragma unroll
    for (int j = 0; j < 8; j++) { cs[j] = 0.f; cq[j] = 0.f; }

#pragma unroll
    for (int r = 0; r < 8; r++) {
        int row = row0 + rg * 8 + r;
        if (row >= NN) continue;
        float o[8];
#pragma unroll
        for (int p = 0; p < 4; p++) {
            float2 u = unpack2(acc[r][p]);
            o[2 * p]     = u.x + bs[2 * p];
            o[2 * p + 1] = u.y + bs[2 * p + 1];
        }
        float4* cp = reinterpret_cast<float4*>(C + (size_t)row * DD + cg * 8);
        cp[0] = make_float4(o[0], o[1], o[2], o[3]);
        cp[1] = make_float4(o[4], o[5], o[6], o[7]);
#pragma unroll
        for (int j = 0; j < 8; j++) {
            cs[j] += o[j];
            cq[j] += o[j] * o[j];
        }
    }
    __syncthreads();
#pragma unroll
    for (int j = 0; j < 8; j++) {
        atomicAdd(&redS[cg * 8 + j], (double)cs[j]);
        atomicAdd(&redQ[cg * 8 + j], (double)cq[j]);
    }
    __syncthreads();
    if (tid < DD) {
        atomicAdd(&g_sum[tid], redS[tid]);
        atomicAdd(&g_sumsq[tid], redQ[tid]);
    }
}

// turn (sum, sumsq, gamma, beta) into affine (a, c); reset accumulators
__global__ void finalize_bn_kernel(const float* __restrict__ g,
                                   const float* __restrict__ b) {
    int j = threadIdx.x;
    double m = g_sum[j] / (double)NN;
    double v = g_sumsq[j] / (double)NN - m * m;
    double a = (double)g[j] / sqrt(v + (double)BN_EPS);
    g_bn_a[j] = (float)a;
    g_bn_c[j] = (float)((double)b[j] - m * a);
    g_sum[j] = 0.0;
    g_sumsq[j] = 0.0;
}

// ---------------- attention pooling + head ----------------------------------
__global__ void scores_kernel(const float* __restrict__ aw,
                              const float* __restrict__ ab) {
    int t = blockIdx.x * blockDim.x + threadIdx.x;
    int i = t >> 5, lane = t & 31;
    if (i >= NN) return;
    const float4* row = reinterpret_cast<const float4*>(g_hr + (size_t)i * HRD);
    const float4* w4 = reinterpret_cast<const float4*>(aw);
    float acc = 0.f;
#pragma unroll
    for (int j = lane; j < HRD / 4; j += 32) {
        float4 r = row[j], w = w4[j];
        acc += r.x * w.x + r.y * w.y + r.z * w.z + r.w * w.w;
    }
#pragma unroll
    for (int off = 16; off; off >>= 1) acc += __shfl_down_sync(0xffffffffu, acc, off);
    if (lane == 0) g_scores[i] = acc + ab[0];
}

__global__ void init_att_kernel() {
    int idx = threadIdx.x;
    if (idx < BB) {
        g_smax[idx] = -CUDART_INF_F;
        g_denom[idx] = 0.f;
    }
}

__global__ void segmax_kernel(const int* __restrict__ gid) {
    int i = blockIdx.x * blockDim.x + threadIdx.x;
    if (i >= NN) return;
    atomicMaxF(&g_smax[gid[i]], g_scores[i]);
}

__global__ void expdenom_kernel(const int* __restrict__ gid) {
    int i = blockIdx.x * blockDim.x + threadIdx.x;
    if (i >= NN) return;
    int g = gid[i];
    float e = expf(g_scores[i] - g_smax[g]);
    g_expv[i] = e;
    atomicAdd(&g_denom[g], e);
}

// graph_id is sorted: one block per graph, binary-search bounds, no atomics.
__global__ void gemb_seg_kernel(const int* __restrict__ gid) {
    __shared__ int s_beg, s_end;
    int b = blockIdx.x, t = threadIdx.x;
    if (t == 0) {
        int lo = 0, hi = NN;
        while (lo < hi) { int m = (lo + hi) >> 1; if (gid[m] < b) lo = m + 1; else hi = m; }
        s_beg = lo;
        lo = 0; hi = NN;
        while (lo < hi) { int m = (lo + hi) >> 1; if (gid[m] < b + 1) lo = m + 1; else hi = m; }
        s_end = lo;
    }
    __syncthreads();
    if (t >= HRD / 4) return;   // 160 active threads, each owns one float4 column
    int beg = s_beg, end = s_end;
    float dn = g_denom[b];
    float4 acc = make_float4(0.f, 0.f, 0.f, 0.f);
    for (int i = beg; i < end; i++) {
        float c = g_expv[i] / dn;
        float4 v = reinterpret_cast<const float4*>(g_hr + (size_t)i * HRD)[t];
        acc.x = fmaf(c, v.x, acc.x);
        acc.y = fmaf(c, v.y, acc.y);
        acc.z = fmaf(c, v.z, acc.z);
        acc.w = fmaf(c, v.w, acc.w);
    }
    reinterpret_cast<float4*>(g_gemb + (size_t)b * HRD)[t] = acc;
}

__global__ void final_kernel(const float* __restrict__ pi,
                             const float* __restrict__ pi_w,
                             const float* __restrict__ pi_b,
                             const float* __restrict__ out_w,
                             const float* __restrict__ out_b,
                             float* __restrict__ out) {
    __shared__ float pie[16];
    int b = blockIdx.x, tid = threadIdx.x;
    if (tid < 16) {
        float a = pi_b[tid];
#pragma unroll
        for (int k = 0; k < 25; k++) a = fmaf(pi[b * 25 + k], pi_w[k * 16 + tid], a);
        pie[tid] = fmaxf(a, 0.f);
    }
    __syncthreads();
    int o = tid >> 5, lane = tid & 31;
    float acc = 0.f;
    const float* ge = g_gemb + (size_t)b * HRD;
    for (int j = lane; j < HRD; j += 32) acc = fmaf(ge[j], out_w[j * NOUT + o], acc);
    if (lane < 16) acc = fmaf(pie[lane], out_w[(HRD + lane) * NOUT + o], acc);
#pragma unroll
    for (int off = 16; off; off >>= 1) acc += __shfl_down_sync(0xffffffffu, acc, off);
    if (lane == 0) out[b * NOUT + o] = acc + out_b[o];
}

// ---------------- launch -----------------------------------------------------
extern "C" void kernel_launch(void* const* d_in, const int* in_sizes, int n_in,
                              void* d_out, int out_size) {
    const float* x    = (const float*)d_in[0];
    const float* pi   = (const float*)d_in[1];
    const float* eps  = (const float*)d_in[2];
    const float* w1   = (const float*)d_in[3];
    const float* b1   = (const float*)d_in[4];
    const float* bng1 = (const float*)d_in[5];
    const float* bnb1 = (const float*)d_in[6];
    const float* w2   = (const float*)d_in[7];
    const float* b2   = (const float*)d_in[8];
    const float* bng  = (const float*)d_in[9];
    const float* bnb  = (const float*)d_in[10];
    const float* aw   = (const float*)d_in[11];
    const float* ab   = (const float*)d_in[12];
    const float* pw   = (const float*)d_in[13];
    const float* pb   = (const float*)d_in[14];
    const float* ow   = (const float*)d_in[15];
    const float* ob   = (const float*)d_in[16];
    const int*   ei   = (const int*)d_in[17];
    const int*   gid  = (const int*)d_in[18];
    const int* src = ei;
    const int* dst = ei + EE;
    float* out = (float*)d_out;

    cudaFuncSetAttribute(gemm128_kernel<false>,
                         cudaFuncAttributeMaxDynamicSharedMemorySize, GEMM_SMEM);
    cudaFuncSetAttribute(gemm128_kernel<true>,
                         cudaFuncAttributeMaxDynamicSharedMemorySize, GEMM_SMEM);

    const int ELT_BLOCKS = (NN * 32 + 255) / 256;          // 6250
    const int GEMM_BLOCKS = (NN + 127) / 128;              // 391
    const int EDGE_BLK = (EE + 255) / 256;                 // 3125

    copy_x_kernel<<<ELT_BLOCKS, 256>>>(x);

    // ---- CSR by dst (once per call) ----
    zero_cnt_kernel<<<(NN + 255) / 256, 256>>>();
    hist_kernel<<<EDGE_BLK, 256>>>(dst);
    scan1_kernel<<<SCAN_BLOCKS, 1024>>>();
    scan2_kernel<<<1, 1>>>();
    scan3_kernel<<<SCAN_BLOCKS, 1024>>>();
    scatter_kernel<<<EDGE_BLK, 256>>>(src, dst);

    for (int l = 0; l < LL; l++) {
        aggregate_kernel<<<ELT_BLOCKS, 256>>>(l, eps);
        gemm128_kernel<false><<<GEMM_BLOCKS, 256, GEMM_SMEM>>>(w1 + (size_t)l * DD * DD,
                                                               b1 + l * DD);
        finalize_bn_kernel<<<1, DD>>>(bng1 + l * DD, bnb1 + l * DD);
        gemm128_kernel<true><<<GEMM_BLOCKS, 256, GEMM_SMEM>>>(w2 + (size_t)l * DD * DD,
                                                              b2 + l * DD);
        finalize_bn_kernel<<<1, DD>>>(bng + l * DD, bnb + l * DD);
        apply_h_kernel<<<ELT_BLOCKS, 256>>>(l);
    }

    scores_kernel<<<ELT_BLOCKS, 256>>>(aw, ab);
    init_att_kernel<<<1, 64>>>();
    segmax_kernel<<<(NN + 255) / 256, 256>>>(gid);
    expdenom_kernel<<<(NN + 255) / 256, 256>>>(gid);
    gemb_seg_kernel<<<BB, 192>>>(gid);
    final_kernel<<<BB, 320>>>(pi, pw, pb, ow, ob, out);
}

// round 5
// speedup vs baseline: 2.0620x; 1.4306x over previous
#include <cuda_runtime.h>
#include <math_constants.h>
#include <math.h>

#define NN 50000
#define EE 800000
#define BB 64
#define DD 128
#define LL 4
#define HRD 640      /* D*(L+1) */
#define NOUT 10
#define BN_EPS 1e-5

#define TILE_R 176   /* GEMM rows per block: ceil(50000/176)=285 <= 296 slots -> 1 wave */

// ---------------- scratch (device globals; no allocation allowed) ----------
__device__ __align__(16) float  g_hr[(size_t)NN * HRD];   // [x | h1 | h2 | h3 | h4]
__device__ __align__(16) float  g_pooled[NN * DD];
__device__ __align__(16) float  g_z1[NN * DD];
__device__ __align__(16) float  g_z2[NN * DD];
__device__ double g_sum[DD];
__device__ double g_sumsq[DD];
__device__ __align__(16) float  g_bn_a[DD];
__device__ __align__(16) float  g_bn_c[DD];
__device__ float  g_scores[NN];
__device__ float  g_expv[NN];
__device__ float  g_smax[BB];
__device__ float  g_denom[BB];
__device__ __align__(16) float  g_gembp[4 * BB * HRD];    // 4 partials per graph
// CSR scratch. Invariants across calls (graph replays):
//   g_cnt  == 0 at call entry (zeroed by scan each call; zero at module load)
//   g_cur  is seeded to rowptr by scan each call BEFORE scatter uses it
__device__ int g_cnt[NN];
__device__ int g_cur[NN];
__device__ int g_rowptr[NN + 1];
__device__ int g_esrc[EE];

// ---------------- packed f32x2 helpers (Blackwell) --------------------------
__device__ __forceinline__ void ffma2(unsigned long long& acc,
                                      unsigned long long a,
                                      unsigned long long b) {
    asm("fma.rn.f32x2 %0, %1, %2, %0;" : "+l"(acc) : "l"(a), "l"(b));
}
__device__ __forceinline__ unsigned long long splat2(float a) {
    unsigned long long r;
    asm("mov.b64 %0, {%1, %1};" : "=l"(r) : "f"(a));
    return r;
}
__device__ __forceinline__ float2 unpack2(unsigned long long v) {
    float2 r;
    asm("mov.b64 {%0, %1}, %2;" : "=f"(r.x), "=f"(r.y) : "l"(v));
    return r;
}

__device__ __forceinline__ void atomicMaxF(float* addr, float val) {
    int old = __float_as_int(*addr);
    while (__int_as_float(old) < val) {
        int assumed = old;
        old = atomicCAS((int*)addr, assumed, __float_as_int(val));
        if (old == assumed) break;
    }
}

// ---------------- CSR construction ------------------------------------------
__global__ void hist_kernel(const int* __restrict__ dst) {
    int e = blockIdx.x * blockDim.x + threadIdx.x;
    if (e < EE) atomicAdd(&g_cnt[dst[e]], 1);
}

// single-block hierarchical scan over 50000 counts.
// Writes rowptr, seeds g_cur = rowptr (scatter cursor), zeroes g_cnt.
__global__ void __launch_bounds__(1024) scan_kernel() {
    __shared__ int wsum[32];
    __shared__ int carry_sh;
    int tid = threadIdx.x, lane = tid & 31, wid = tid >> 5;
    if (tid == 0) carry_sh = 0;
    __syncthreads();
    for (int t = 0; t < 49; t++) {
        int g = t * 1024 + tid;
        int v = (g < NN) ? g_cnt[g] : 0;
        if (g < NN) g_cnt[g] = 0;
        int carry = carry_sh;
        // warp inclusive scan
        int s = v;
#pragma unroll
        for (int off = 1; off < 32; off <<= 1) {
            int u = __shfl_up_sync(0xffffffffu, s, off);
            if (lane >= off) s += u;
        }
        if (lane == 31) wsum[wid] = s;
        __syncthreads();
        if (wid == 0) {
            int ws = wsum[lane];
#pragma unroll
            for (int off = 1; off < 32; off <<= 1) {
                int u = __shfl_up_sync(0xffffffffu, ws, off);
                if (lane >= off) ws += u;
            }
            wsum[lane] = ws;
        }
        __syncthreads();
        int wpre = (wid == 0) ? 0 : wsum[wid - 1];
        if (g < NN) {
            int rp = carry + wpre + s - v;
            g_rowptr[g] = rp;
            g_cur[g] = rp;          // scatter cursor seeded fresh every call
        }
        __syncthreads();
        if (tid == 1023) carry_sh = carry + wsum[31];
        __syncthreads();
    }
    if (tid == 0) g_rowptr[NN] = EE;
}

__global__ void scatter_kernel(const int* __restrict__ src,
                               const int* __restrict__ dst) {
    int e = blockIdx.x * blockDim.x + threadIdx.x;
    if (e >= EE) return;
    int d = dst[e];
    int p = atomicAdd(&g_cur[d], 1);   // cursor pre-seeded to rowptr[d]
    g_esrc[p] = src[e];
}

// ---------------- aggregation (gather via CSR) -------------------------------
// pooled[i] = sum_{incoming} h[src] + (1+eps[l])*h[i]
// NOTE: h source pointer resolved in DEVICE code (host must not touch g_hr).
__global__ void aggregate_kernel(const float* __restrict__ x,
                                 const float* __restrict__ eps, int l) {
    int idx = blockIdx.x * blockDim.x + threadIdx.x;
    int i = idx >> 5, lane = idx & 31;
    if (i >= NN) return;
    const float* hsrc = (l == 0) ? x : (g_hr + (size_t)l * DD);
    const int stride = (l == 0) ? DD : HRD;
    int beg = g_rowptr[i], end = g_rowptr[i + 1];
    float4 acc = make_float4(0.f, 0.f, 0.f, 0.f);
    int e = beg;
    for (; e + 3 < end; e += 4) {
        int s0 = g_esrc[e], s1 = g_esrc[e + 1], s2 = g_esrc[e + 2], s3 = g_esrc[e + 3];
        float4 v0 = reinterpret_cast<const float4*>(hsrc + (size_t)s0 * stride)[lane];
        float4 v1 = reinterpret_cast<const float4*>(hsrc + (size_t)s1 * stride)[lane];
        float4 v2 = reinterpret_cast<const float4*>(hsrc + (size_t)s2 * stride)[lane];
        float4 v3 = reinterpret_cast<const float4*>(hsrc + (size_t)s3 * stride)[lane];
        acc.x += (v0.x + v1.x) + (v2.x + v3.x);
        acc.y += (v0.y + v1.y) + (v2.y + v3.y);
        acc.z += (v0.z + v1.z) + (v2.z + v3.z);
        acc.w += (v0.w + v1.w) + (v2.w + v3.w);
    }
    for (; e < end; e++) {
        int s0 = g_esrc[e];
        float4 v0 = reinterpret_cast<const float4*>(hsrc + (size_t)s0 * stride)[lane];
        acc.x += v0.x; acc.y += v0.y; acc.z += v0.z; acc.w += v0.w;
    }
    float sc = 1.0f + eps[l];
    float4 h = reinterpret_cast<const float4*>(hsrc + (size_t)i * stride)[lane];
    acc.x = fmaf(sc, h.x, acc.x);
    acc.y = fmaf(sc, h.y, acc.y);
    acc.z = fmaf(sc, h.z, acc.z);
    acc.w = fmaf(sc, h.w, acc.w);
    reinterpret_cast<float4*>(g_pooled + (size_t)i * DD)[lane] = acc;
}

// ---------------- elementwise / fused score kernels --------------------------
// copy x into hr slab AND initialize scores with x-segment dot
__global__ void copyx_scores_kernel(const float* __restrict__ x,
                                    const float* __restrict__ aw,
                                    const float* __restrict__ ab) {
    int idx = blockIdx.x * blockDim.x + threadIdx.x;
    if (idx >= NN * 32) return;
    int i = idx >> 5, c = idx & 31;
    float4 v = reinterpret_cast<const float4*>(x + (size_t)i * DD)[c];
    reinterpret_cast<float4*>(g_hr + (size_t)i * HRD)[c] = v;
    float4 w = reinterpret_cast<const float4*>(aw)[c];
    float s = v.x * w.x + v.y * w.y + v.z * w.z + v.w * w.w;
#pragma unroll
    for (int off = 16; off; off >>= 1) s += __shfl_down_sync(0xffffffffu, s, off);
    if ((idx & 31) == 0) g_scores[i] = s + ab[0];
}

// h_{l+1} = relu(a*z2 + c) -> hr slab; accumulate score segment
__global__ void apply_h_kernel(int l, const float* __restrict__ aw) {
    int idx = blockIdx.x * blockDim.x + threadIdx.x;
    if (idx >= NN * 32) return;
    int i = idx >> 5, c = idx & 31;
    float4 z = reinterpret_cast<const float4*>(g_z2 + (size_t)i * DD)[c];
    float4 a = reinterpret_cast<const float4*>(g_bn_a)[c];
    float4 b = reinterpret_cast<const float4*>(g_bn_c)[c];
    float4 o;
    o.x = fmaxf(fmaf(a.x, z.x, b.x), 0.f);
    o.y = fmaxf(fmaf(a.y, z.y, b.y), 0.f);
    o.z = fmaxf(fmaf(a.z, z.z, b.z), 0.f);
    o.w = fmaxf(fmaf(a.w, z.w, b.w), 0.f);
    reinterpret_cast<float4*>(g_hr + (size_t)i * HRD + (size_t)(l + 1) * DD)[c] = o;
    float4 w = reinterpret_cast<const float4*>(aw)[(l + 1) * 32 + c];
    float s = o.x * w.x + o.y * w.y + o.z * w.z + o.w * w.w;
#pragma unroll
    for (int off = 16; off; off >>= 1) s += __shfl_down_sync(0xffffffffu, s, off);
    if ((idx & 31) == 0) g_scores[i] += s;
}

// ---------------- GEMM: C[TILE_R rows,128] = A @ W + b; col stats in fp64 ----
#define GEMM_SMEM (TILE_R * DD * 4 + 2 * DD * 8)

template <bool SECOND>
__global__ void __launch_bounds__(256, 2) gemm128_kernel(const float* __restrict__ W,
                                                         const float* __restrict__ bias) {
    extern __shared__ float smem[];
    float* Ash = smem;                                        // TILE_R x 128
    double* redS = reinterpret_cast<double*>(smem + TILE_R * DD);
    double* redQ = redS + DD;

    const float* A = SECOND ? g_z1 : g_pooled;
    float* C       = SECOND ? g_z2 : g_z1;

    int tid = threadIdx.x;
    if (tid < DD) { redS[tid] = 0.0; redQ[tid] = 0.0; }

    int row0 = blockIdx.x * TILE_R;
    {
        float4* As = reinterpret_cast<float4*>(Ash);
#pragma unroll
        for (int ii = 0; ii < TILE_R * 32 / 256; ii++) {
            int i = tid + ii * 256;             // float4 index
            int r = i >> 5, c4 = i & 31;
            int row = row0 + r;
            float4 v = make_float4(0.f, 0.f, 0.f, 0.f);
            if (row < NN)
                v = *reinterpret_cast<const float4*>(A + (size_t)row * DD + c4 * 4);
            if (SECOND) {
                float4 ba = reinterpret_cast<const float4*>(g_bn_a)[c4];
                float4 bc = reinterpret_cast<const float4*>(g_bn_c)[c4];
                v.x = fmaxf(fmaf(ba.x, v.x, bc.x), 0.f);
                v.y = fmaxf(fmaf(ba.y, v.y, bc.y), 0.f);
                v.z = fmaxf(fmaf(ba.z, v.z, bc.z), 0.f);
                v.w = fmaxf(fmaf(ba.w, v.w, bc.w), 0.f);
            }
            As[i] = v;
        }
    }
    __syncthreads();

    const int RPT = TILE_R / 16;    // 11 rows per thread
    int cg = tid & 15;              // 8 columns: 8*cg .. 8*cg+7
    int rg = tid >> 4;              // rows rg*RPT .. rg*RPT+RPT-1
    const float* arow = Ash + rg * RPT * DD;
    const ulonglong2* Wg = reinterpret_cast<const ulonglong2*>(W);

    unsigned long long acc[RPT][4];
#pragma unroll
    for (int r = 0; r < RPT; r++)
#pragma unroll
        for (int p = 0; p < 4; p++) acc[r][p] = 0ull;

#pragma unroll 2
    for (int k = 0; k < DD; k++) {
        ulonglong2 wA = __ldg(&Wg[k * 32 + cg * 2]);
        ulonglong2 wB = __ldg(&Wg[k * 32 + cg * 2 + 1]);
#pragma unroll
        for (int r = 0; r < RPT; r++) {
            unsigned long long a2 = splat2(arow[r * DD + k]);
            ffma2(acc[r][0], a2, wA.x);
            ffma2(acc[r][1], a2, wA.y);
            ffma2(acc[r][2], a2, wB.x);
            ffma2(acc[r][3], a2, wB.y);
        }
    }

    float bs[8];
#pragma unroll
    for (int j = 0; j < 8; j++) bs[j] = bias[cg * 8 + j];

    float cs[8], cq[8];
#pragma unroll
    for (int j = 0; j < 8; j++) { cs[j] = 0.f; cq[j] = 0.f; }

#pragma unroll
    for (int r = 0; r < RPT; r++) {
        int row = row0 + rg * RPT + r;
        if (row >= NN) continue;
        float o[8];
#pragma unroll
        for (int p = 0; p < 4; p++) {
            float2 u = unpack2(acc[r][p]);
            o[2 * p]     = u.x + bs[2 * p];
            o[2 * p + 1] = u.y + bs[2 * p + 1];
        }
        float4* cp = reinterpret_cast<float4*>(C + (size_t)row * DD + cg * 8);
        cp[0] = make_float4(o[0], o[1], o[2], o[3]);
        cp[1] = make_float4(o[4], o[5], o[6], o[7]);
#pragma unroll
        for (int j = 0; j < 8; j++) {
            cs[j] += o[j];
            cq[j] += o[j] * o[j];
        }
    }
    __syncthreads();
#pragma unroll
    for (int j = 0; j < 8; j++) {
        atomicAdd(&redS[cg * 8 + j], (double)cs[j]);
        atomicAdd(&redQ[cg * 8 + j], (double)cq[j]);
    }
    __syncthreads();
    if (tid < DD) {
        atomicAdd(&g_sum[tid], redS[tid]);
        atomicAdd(&g_sumsq[tid], redQ[tid]);
    }
}

// turn (sum, sumsq, gamma, beta) into affine (a, c); reset accumulators
__global__ void finalize_bn_kernel(const float* __restrict__ g,
                                   const float* __restrict__ b) {
    int j = threadIdx.x;
    double m = g_sum[j] / (double)NN;
    double v = g_sumsq[j] / (double)NN - m * m;
    double a = (double)g[j] / sqrt(v + (double)BN_EPS);
    g_bn_a[j] = (float)a;
    g_bn_c[j] = (float)((double)b[j] - m * a);
    g_sum[j] = 0.0;
    g_sumsq[j] = 0.0;
}

// ---------------- attention pooling + head ----------------------------------
__global__ void init_att_kernel() {
    int idx = threadIdx.x;
    if (idx < BB) {
        g_smax[idx] = -CUDART_INF_F;
        g_denom[idx] = 0.f;
    }
}

__global__ void segmax_kernel(const int* __restrict__ gid) {
    int i = blockIdx.x * blockDim.x + threadIdx.x;
    if (i >= NN) return;
    atomicMaxF(&g_smax[gid[i]], g_scores[i]);
}

__global__ void expdenom_kernel(const int* __restrict__ gid) {
    int i = blockIdx.x * blockDim.x + threadIdx.x;
    if (i >= NN) return;
    int g = gid[i];
    float e = expf(g_scores[i] - g_smax[g]);
    g_expv[i] = e;
    atomicAdd(&g_denom[g], e);
}

// 4 blocks per graph; each writes one partial slab (atomic-free)
__global__ void gemb_part_kernel(const int* __restrict__ gid) {
    __shared__ int s_beg, s_end;
    int b = blockIdx.x >> 2, q = blockIdx.x & 3, t = threadIdx.x;
    if (t == 0) {
        int lo = 0, hi = NN;
        while (lo < hi) { int m = (lo + hi) >> 1; if (gid[m] < b) lo = m + 1; else hi = m; }
        s_beg = lo;
        lo = 0; hi = NN;
        while (lo < hi) { int m = (lo + hi) >> 1; if (gid[m] < b + 1) lo = m + 1; else hi = m; }
        s_end = lo;
    }
    __syncthreads();
    if (t >= HRD / 4) return;   // 160 active threads, one float4 column each
    int beg = s_beg, len = s_end - s_beg;
    int qb = beg + (int)(((long long)len * q) >> 2);
    int qe = beg + (int)(((long long)len * (q + 1)) >> 2);
    float dn = g_denom[b];
    float4 acc = make_float4(0.f, 0.f, 0.f, 0.f);
    for (int i = qb; i < qe; i++) {
        float c = g_expv[i] / dn;
        float4 v = reinterpret_cast<const float4*>(g_hr + (size_t)i * HRD)[t];
        acc.x = fmaf(c, v.x, acc.x);
        acc.y = fmaf(c, v.y, acc.y);
        acc.z = fmaf(c, v.z, acc.z);
        acc.w = fmaf(c, v.w, acc.w);
    }
    reinterpret_cast<float4*>(g_gembp + (size_t)blockIdx.x * HRD)[t] = acc;
}

__global__ void final_kernel(const float* __restrict__ pi,
                             const float* __restrict__ pi_w,
                             const float* __restrict__ pi_b,
                             const float* __restrict__ out_w,
                             const float* __restrict__ out_b,
                             float* __restrict__ out) {
    __shared__ float pie[16];
    int b = blockIdx.x, tid = threadIdx.x;
    if (tid < 16) {
        float a = pi_b[tid];
#pragma unroll
        for (int k = 0; k < 25; k++) a = fmaf(pi[b * 25 + k], pi_w[k * 16 + tid], a);
        pie[tid] = fmaxf(a, 0.f);
    }
    __syncthreads();
    int o = tid >> 5, lane = tid & 31;
    float acc = 0.f;
    const float* g0 = g_gembp + (size_t)(b * 4 + 0) * HRD;
    const float* g1 = g_gembp + (size_t)(b * 4 + 1) * HRD;
    const float* g2 = g_gembp + (size_t)(b * 4 + 2) * HRD;
    const float* g3 = g_gembp + (size_t)(b * 4 + 3) * HRD;
    for (int j = lane; j < HRD; j += 32) {
        float ge = (g0[j] + g1[j]) + (g2[j] + g3[j]);
        acc = fmaf(ge, out_w[j * NOUT + o], acc);
    }
    if (lane < 16) acc = fmaf(pie[lane], out_w[(HRD + lane) * NOUT + o], acc);
#pragma unroll
    for (int off = 16; off; off >>= 1) acc += __shfl_down_sync(0xffffffffu, acc, off);
    if (lane == 0) out[b * NOUT + o] = acc + out_b[o];
}

// ---------------- launch -----------------------------------------------------
extern "C" void kernel_launch(void* const* d_in, const int* in_sizes, int n_in,
                              void* d_out, int out_size) {
    const float* x    = (const float*)d_in[0];
    const float* pi   = (const float*)d_in[1];
    const float* eps  = (const float*)d_in[2];
    const float* w1   = (const float*)d_in[3];
    const float* b1   = (const float*)d_in[4];
    const float* bng1 = (const float*)d_in[5];
    const float* bnb1 = (const float*)d_in[6];
    const float* w2   = (const float*)d_in[7];
    const float* b2   = (const float*)d_in[8];
    const float* bng  = (const float*)d_in[9];
    const float* bnb  = (const float*)d_in[10];
    const float* aw   = (const float*)d_in[11];
    const float* ab   = (const float*)d_in[12];
    const float* pw   = (const float*)d_in[13];
    const float* pb   = (const float*)d_in[14];
    const float* ow   = (const float*)d_in[15];
    const float* ob   = (const float*)d_in[16];
    const int*   ei   = (const int*)d_in[17];
    const int*   gid  = (const int*)d_in[18];
    const int* src = ei;
    const int* dst = ei + EE;
    float* out = (float*)d_out;

    cudaFuncSetAttribute(gemm128_kernel<false>,
                         cudaFuncAttributeMaxDynamicSharedMemorySize, GEMM_SMEM);
    cudaFuncSetAttribute(gemm128_kernel<true>,
                         cudaFuncAttributeMaxDynamicSharedMemorySize, GEMM_SMEM);

    const int ELT_BLOCKS = (NN * 32 + 255) / 256;          // 6250
    const int GEMM_BLOCKS = (NN + TILE_R - 1) / TILE_R;    // 285
    const int EDGE_BLK = (EE + 255) / 256;                 // 3125

    // ---- CSR by dst; g_cnt==0 at entry, scan re-zeroes it and seeds g_cur ----
    hist_kernel<<<EDGE_BLK, 256>>>(dst);                   // launch 1
    scan_kernel<<<1, 1024>>>();                            // launch 2
    scatter_kernel<<<EDGE_BLK, 256>>>(src, dst);           // launch 3

    for (int l = 0; l < LL; l++) {
        aggregate_kernel<<<ELT_BLOCKS, 256>>>(x, eps, l);  // launch 4 (profiled, l=0)
        if (l == 0) copyx_scores_kernel<<<ELT_BLOCKS, 256>>>(x, aw, ab);
        gemm128_kernel<false><<<GEMM_BLOCKS, 256, GEMM_SMEM>>>(w1 + (size_t)l * DD * DD,
                                                               b1 + l * DD);
        finalize_bn_kernel<<<1, DD>>>(bng1 + l * DD, bnb1 + l * DD);
        gemm128_kernel<true><<<GEMM_BLOCKS, 256, GEMM_SMEM>>>(w2 + (size_t)l * DD * DD,
                                                              b2 + l * DD);
        finalize_bn_kernel<<<1, DD>>>(bng + l * DD, bnb + l * DD);
        apply_h_kernel<<<ELT_BLOCKS, 256>>>(l, aw);
    }

    init_att_kernel<<<1, 64>>>();
    segmax_kernel<<<(NN + 255) / 256, 256>>>(gid);
    expdenom_kernel<<<(NN + 255) / 256, 256>>>(gid);
    gemb_part_kernel<<<4 * BB, 192>>>(gid);
    final_kernel<<<BB, 320>>>(pi, pw, pb, ow, ob, out);
}

// round 6
// speedup vs baseline: 2.2248x; 1.0789x over previous
#include <cuda_runtime.h>
#include <math_constants.h>
#include <math.h>

#define NN 50000
#define EE 800000
#define BB 64
#define DD 128
#define LL 4
#define HRD 640      /* D*(L+1) */
#define NOUT 10
#define BN_EPS 1e-5

#define TILE_R 176   /* GEMM rows per block: ceil(50000/176)=285 <= 296 slots -> 1 wave */
#define ASTRIDE 132  /* padded smem row stride (floats): rg groups hit distinct banks */
#define RPT (TILE_R / 16)   /* 11 rows per thread */

// ---------------- scratch (device globals; no allocation allowed) ----------
__device__ __align__(16) float  g_hr[(size_t)NN * HRD];   // [x | h1 | h2 | h3 | h4]
__device__ __align__(16) float  g_z1[NN * DD];
__device__ __align__(16) float  g_z2[NN * DD];
__device__ double g_sum[DD];
__device__ double g_sumsq[DD];
__device__ __align__(16) float  g_bn_a[DD];
__device__ __align__(16) float  g_bn_c[DD];
__device__ float  g_scores[NN];
__device__ __align__(16) float  g_gembp[4 * BB * HRD];    // 4 partials per graph
// CSR scratch. Invariants across calls (graph replays):
//   g_cnt == 0 at call entry (zeroed by scan each call; zero at module load)
//   g_cur is seeded to rowptr by scan each call BEFORE scatter uses it
__device__ int g_cnt[NN];
__device__ int g_cur[NN];
__device__ int g_rowptr[NN + 1];
__device__ int g_esrc[EE];

// ---------------- packed f32x2 helpers (Blackwell) --------------------------
__device__ __forceinline__ void ffma2(unsigned long long& acc,
                                      unsigned long long a,
                                      unsigned long long b) {
    asm("fma.rn.f32x2 %0, %1, %2, %0;" : "+l"(acc) : "l"(a), "l"(b));
}
__device__ __forceinline__ unsigned long long splat2(float a) {
    unsigned long long r;
    asm("mov.b64 %0, {%1, %1};" : "=l"(r) : "f"(a));
    return r;
}
__device__ __forceinline__ float2 unpack2(unsigned long long v) {
    float2 r;
    asm("mov.b64 {%0, %1}, %2;" : "=f"(r.x), "=f"(r.y) : "l"(v));
    return r;
}

// ---------------- CSR construction ------------------------------------------
__global__ void hist_kernel(const int* __restrict__ dst) {
    int e = blockIdx.x * blockDim.x + threadIdx.x;
    if (e < EE) atomicAdd(&g_cnt[dst[e]], 1);
}

// single-block hierarchical scan over 50000 counts.
// Writes rowptr, seeds g_cur = rowptr (scatter cursor), zeroes g_cnt.
__global__ void __launch_bounds__(1024) scan_kernel() {
    __shared__ int wsum[32];
    __shared__ int carry_sh;
    int tid = threadIdx.x, lane = tid & 31, wid = tid >> 5;
    if (tid == 0) carry_sh = 0;
    __syncthreads();
    for (int t = 0; t < 49; t++) {
        int g = t * 1024 + tid;
        int v = (g < NN) ? g_cnt[g] : 0;
        if (g < NN) g_cnt[g] = 0;
        int carry = carry_sh;
        int s = v;
#pragma unroll
        for (int off = 1; off < 32; off <<= 1) {
            int u = __shfl_up_sync(0xffffffffu, s, off);
            if (lane >= off) s += u;
        }
        if (lane == 31) wsum[wid] = s;
        __syncthreads();
        if (wid == 0) {
            int ws = wsum[lane];
#pragma unroll
            for (int off = 1; off < 32; off <<= 1) {
                int u = __shfl_up_sync(0xffffffffu, ws, off);
                if (lane >= off) ws += u;
            }
            wsum[lane] = ws;
        }
        __syncthreads();
        int wpre = (wid == 0) ? 0 : wsum[wid - 1];
        if (g < NN) {
            int rp = carry + wpre + s - v;
            g_rowptr[g] = rp;
            g_cur[g] = rp;          // scatter cursor seeded fresh every call
        }
        __syncthreads();
        if (tid == 1023) carry_sh = carry + wsum[31];
        __syncthreads();
    }
    if (tid == 0) g_rowptr[NN] = EE;
}

__global__ void scatter_kernel(const int* __restrict__ src,
                               const int* __restrict__ dst) {
    int e = blockIdx.x * blockDim.x + threadIdx.x;
    if (e >= EE) return;
    int d = dst[e];
    int p = atomicAdd(&g_cur[d], 1);   // cursor pre-seeded to rowptr[d]
    g_esrc[p] = src[e];
}

// ---------------- elementwise / fused score kernels --------------------------
// copy x into hr slab AND initialize scores with x-segment dot
__global__ void copyx_scores_kernel(const float* __restrict__ x,
                                    const float* __restrict__ aw,
                                    const float* __restrict__ ab) {
    int idx = blockIdx.x * blockDim.x + threadIdx.x;
    if (idx >= NN * 32) return;
    int i = idx >> 5, c = idx & 31;
    float4 v = reinterpret_cast<const float4*>(x + (size_t)i * DD)[c];
    reinterpret_cast<float4*>(g_hr + (size_t)i * HRD)[c] = v;
    float4 w = reinterpret_cast<const float4*>(aw)[c];
    float s = v.x * w.x + v.y * w.y + v.z * w.z + v.w * w.w;
#pragma unroll
    for (int off = 16; off; off >>= 1) s += __shfl_down_sync(0xffffffffu, s, off);
    if ((idx & 31) == 0) g_scores[i] = s + ab[0];
}

// h_{l+1} = relu(a*z2 + c) -> hr slab; accumulate score segment
__global__ void apply_h_kernel(int l, const float* __restrict__ aw) {
    int idx = blockIdx.x * blockDim.x + threadIdx.x;
    if (idx >= NN * 32) return;
    int i = idx >> 5, c = idx & 31;
    float4 z = reinterpret_cast<const float4*>(g_z2 + (size_t)i * DD)[c];
    float4 a = reinterpret_cast<const float4*>(g_bn_a)[c];
    float4 b = reinterpret_cast<const float4*>(g_bn_c)[c];
    float4 o;
    o.x = fmaxf(fmaf(a.x, z.x, b.x), 0.f);
    o.y = fmaxf(fmaf(a.y, z.y, b.y), 0.f);
    o.z = fmaxf(fmaf(a.z, z.z, b.z), 0.f);
    o.w = fmaxf(fmaf(a.w, z.w, b.w), 0.f);
    reinterpret_cast<float4*>(g_hr + (size_t)i * HRD + (size_t)(l + 1) * DD)[c] = o;
    float4 w = reinterpret_cast<const float4*>(aw)[(l + 1) * 32 + c];
    float s = o.x * w.x + o.y * w.y + o.z * w.z + o.w * w.w;
#pragma unroll
    for (int off = 16; off; off >>= 1) s += __shfl_down_sync(0xffffffffu, s, off);
    if ((idx & 31) == 0) g_scores[i] += s;
}

// ---------------- GEMM (TILE_R x 128) @ W[128,128] + b; col stats in fp64 ----
// FUSED=true : A-tile built by CSR gather: A[i] = sum_nbr h[src] + (1+eps)*h[i]
// FUSED=false: A = relu(bn_a * g_z1 + bn_c)   (MLP second linear)
#define GEMM_SMEM (TILE_R * ASTRIDE * 4 + 2 * DD * 8)

template <bool FUSED>
__global__ void __launch_bounds__(256, 2) gemm128_kernel(const float* __restrict__ W,
                                                         const float* __restrict__ bias,
                                                         const float* __restrict__ x,
                                                         const float* __restrict__ eps,
                                                         int l) {
    extern __shared__ float smem[];
    float* Ash = smem;                                        // TILE_R x ASTRIDE
    double* redS = reinterpret_cast<double*>(smem + TILE_R * ASTRIDE);
    double* redQ = redS + DD;

    float* C = FUSED ? g_z1 : g_z2;

    int tid = threadIdx.x;
    if (tid < DD) { redS[tid] = 0.0; redQ[tid] = 0.0; }

    int row0 = blockIdx.x * TILE_R;

    if (FUSED) {
        // ---- gather phase: 8 warps x 22 rows, lane owns one float4 column ----
        const float* hsrc = (l == 0) ? x : (g_hr + (size_t)l * DD);
        const int stride = (l == 0) ? DD : HRD;
        const float sc = 1.0f + eps[l];
        int wid = tid >> 5, lane = tid & 31;
#pragma unroll 1
        for (int rr = 0; rr < TILE_R / 8; rr++) {
            int r = wid * (TILE_R / 8) + rr;
            int row = row0 + r;
            float4 acc = make_float4(0.f, 0.f, 0.f, 0.f);
            if (row < NN) {
                int beg = g_rowptr[row], end = g_rowptr[row + 1];
                int e = beg;
                for (; e + 3 < end; e += 4) {
                    int s0 = g_esrc[e], s1 = g_esrc[e + 1];
                    int s2 = g_esrc[e + 2], s3 = g_esrc[e + 3];
                    float4 v0 = reinterpret_cast<const float4*>(hsrc + (size_t)s0 * stride)[lane];
                    float4 v1 = reinterpret_cast<const float4*>(hsrc + (size_t)s1 * stride)[lane];
                    float4 v2 = reinterpret_cast<const float4*>(hsrc + (size_t)s2 * stride)[lane];
                    float4 v3 = reinterpret_cast<const float4*>(hsrc + (size_t)s3 * stride)[lane];
                    acc.x += (v0.x + v1.x) + (v2.x + v3.x);
                    acc.y += (v0.y + v1.y) + (v2.y + v3.y);
                    acc.z += (v0.z + v1.z) + (v2.z + v3.z);
                    acc.w += (v0.w + v1.w) + (v2.w + v3.w);
                }
                for (; e < end; e++) {
                    int s0 = g_esrc[e];
                    float4 v0 = reinterpret_cast<const float4*>(hsrc + (size_t)s0 * stride)[lane];
                    acc.x += v0.x; acc.y += v0.y; acc.z += v0.z; acc.w += v0.w;
                }
                float4 h = reinterpret_cast<const float4*>(hsrc + (size_t)row * stride)[lane];
                acc.x = fmaf(sc, h.x, acc.x);
                acc.y = fmaf(sc, h.y, acc.y);
                acc.z = fmaf(sc, h.z, acc.z);
                acc.w = fmaf(sc, h.w, acc.w);
            }
            *reinterpret_cast<float4*>(Ash + r * ASTRIDE + lane * 4) = acc;
        }
    } else {
        // ---- load phase: g_z1 with BN affine + ReLU ----
#pragma unroll
        for (int ii = 0; ii < TILE_R * 32 / 256; ii++) {
            int i = tid + ii * 256;             // float4 index over tile
            int r = i >> 5, c4 = i & 31;
            int row = row0 + r;
            float4 v = make_float4(0.f, 0.f, 0.f, 0.f);
            if (row < NN) {
                v = *reinterpret_cast<const float4*>(g_z1 + (size_t)row * DD + c4 * 4);
                float4 ba = reinterpret_cast<const float4*>(g_bn_a)[c4];
                float4 bc = reinterpret_cast<const float4*>(g_bn_c)[c4];
                v.x = fmaxf(fmaf(ba.x, v.x, bc.x), 0.f);
                v.y = fmaxf(fmaf(ba.y, v.y, bc.y), 0.f);
                v.z = fmaxf(fmaf(ba.z, v.z, bc.z), 0.f);
                v.w = fmaxf(fmaf(ba.w, v.w, bc.w), 0.f);
            }
            *reinterpret_cast<float4*>(Ash + r * ASTRIDE + c4 * 4) = v;
        }
    }
    __syncthreads();

    int cg = tid & 15;   // 8 columns: 8*cg .. 8*cg+7
    int rg = tid >> 4;   // rows rg*RPT .. rg*RPT+RPT-1
    const float* arow = Ash + rg * RPT * ASTRIDE;
    const ulonglong2* Wg = reinterpret_cast<const ulonglong2*>(W);

    unsigned long long acc[RPT][4];
#pragma unroll
    for (int r = 0; r < RPT; r++)
#pragma unroll
        for (int p = 0; p < 4; p++) acc[r][p] = 0ull;

#pragma unroll 2
    for (int k = 0; k < DD; k++) {
        ulonglong2 wA = __ldg(&Wg[k * 32 + cg * 2]);
        ulonglong2 wB = __ldg(&Wg[k * 32 + cg * 2 + 1]);
#pragma unroll
        for (int r = 0; r < RPT; r++) {
            unsigned long long a2 = splat2(arow[r * ASTRIDE + k]);
            ffma2(acc[r][0], a2, wA.x);
            ffma2(acc[r][1], a2, wA.y);
            ffma2(acc[r][2], a2, wB.x);
            ffma2(acc[r][3], a2, wB.y);
        }
    }

    float bs[8];
#pragma unroll
    for (int j = 0; j < 8; j++) bs[j] = bias[cg * 8 + j];

    float cs[8], cq[8];
#pragma unroll
    for (int j = 0; j < 8; j++) { cs[j] = 0.f; cq[j] = 0.f; }

#pragma unroll
    for (int r = 0; r < RPT; r++) {
        int row = row0 + rg * RPT + r;
        if (row >= NN) continue;
        float o[8];
#pragma unroll
        for (int p = 0; p < 4; p++) {
            float2 u = unpack2(acc[r][p]);
            o[2 * p]     = u.x + bs[2 * p];
            o[2 * p + 1] = u.y + bs[2 * p + 1];
        }
        float4* cp = reinterpret_cast<float4*>(C + (size_t)row * DD + cg * 8);
        cp[0] = make_float4(o[0], o[1], o[2], o[3]);
        cp[1] = make_float4(o[4], o[5], o[6], o[7]);
#pragma unroll
        for (int j = 0; j < 8; j++) {
            cs[j] += o[j];
            cq[j] += o[j] * o[j];
        }
    }
    __syncthreads();
#pragma unroll
    for (int j = 0; j < 8; j++) {
        atomicAdd(&redS[cg * 8 + j], (double)cs[j]);
        atomicAdd(&redQ[cg * 8 + j], (double)cq[j]);
    }
    __syncthreads();
    if (tid < DD) {
        atomicAdd(&g_sum[tid], redS[tid]);
        atomicAdd(&g_sumsq[tid], redQ[tid]);
    }
}

// turn (sum, sumsq, gamma, beta) into affine (a, c); reset accumulators
__global__ void finalize_bn_kernel(const float* __restrict__ g,
                                   const float* __restrict__ b) {
    int j = threadIdx.x;
    double m = g_sum[j] / (double)NN;
    double v = g_sumsq[j] / (double)NN - m * m;
    double a = (double)g[j] / sqrt(v + (double)BN_EPS);
    g_bn_a[j] = (float)a;
    g_bn_c[j] = (float)((double)b[j] - m * a);
    g_sum[j] = 0.0;
    g_sumsq[j] = 0.0;
}

// ---------------- attention pooling + head ----------------------------------
// 4 blocks per graph; each computes segment max+denom (redundant, cheap) and
// its quarter of the weighted sum. Atomic-free.
#define ECHUNK 512
__global__ void __launch_bounds__(256) gemb_part_kernel(const int* __restrict__ gid) {
    __shared__ int s_beg, s_end;
    __shared__ float red[32];
    __shared__ float s_mx, s_dn;
    __shared__ float ecache[ECHUNK];
    int b = blockIdx.x >> 2, q = blockIdx.x & 3, t = threadIdx.x;
    int lane = t & 31, wid = t >> 5;
    if (t == 0) {
        int lo = 0, hi = NN;
        while (lo < hi) { int m = (lo + hi) >> 1; if (gid[m] < b) lo = m + 1; else hi = m; }
        s_beg = lo;
        lo = 0; hi = NN;
        while (lo < hi) { int m = (lo + hi) >> 1; if (gid[m] < b + 1) lo = m + 1; else hi = m; }
        s_end = lo;
    }
    __syncthreads();
    int beg = s_beg, end = s_end;

    // segment max
    float mx = -CUDART_INF_F;
    for (int i = beg + t; i < end; i += 256) mx = fmaxf(mx, g_scores[i]);
#pragma unroll
    for (int off = 16; off; off >>= 1) mx = fmaxf(mx, __shfl_xor_sync(0xffffffffu, mx, off));
    if (lane == 0) red[wid] = mx;
    __syncthreads();
    if (wid == 0) {
        float m2 = (lane < 8) ? red[lane] : -CUDART_INF_F;
#pragma unroll
        for (int off = 4; off; off >>= 1) m2 = fmaxf(m2, __shfl_xor_sync(0xffffffffu, m2, off));
        if (lane == 0) s_mx = m2;
    }
    __syncthreads();
    float smax = s_mx;

    // segment denom
    float dn = 0.f;
    for (int i = beg + t; i < end; i += 256) dn += expf(g_scores[i] - smax);
#pragma unroll
    for (int off = 16; off; off >>= 1) dn += __shfl_xor_sync(0xffffffffu, dn, off);
    if (lane == 0) red[wid] = dn;
    __syncthreads();
    if (wid == 0) {
        float d2 = (lane < 8) ? red[lane] : 0.f;
#pragma unroll
        for (int off = 4; off; off >>= 1) d2 += __shfl_xor_sync(0xffffffffu, d2, off);
        if (lane == 0) s_dn = d2;
    }
    __syncthreads();
    float denom = s_dn;

    // quarter bounds
    int len = end - beg;
    int qb = beg + (int)(((long long)len * q) >> 2);
    int qe = beg + (int)(((long long)len * (q + 1)) >> 2);

    float4 acc = make_float4(0.f, 0.f, 0.f, 0.f);
    for (int chunk = qb; chunk < qe; chunk += ECHUNK) {
        int ce = chunk + ECHUNK < qe ? chunk + ECHUNK : qe;
        for (int i = chunk + t; i < ce; i += 256)
            ecache[i - chunk] = expf(g_scores[i] - smax) / denom;
        __syncthreads();
        if (t < HRD / 4) {
            for (int i = chunk; i < ce; i++) {
                float c = ecache[i - chunk];
                float4 v = reinterpret_cast<const float4*>(g_hr + (size_t)i * HRD)[t];
                acc.x = fmaf(c, v.x, acc.x);
                acc.y = fmaf(c, v.y, acc.y);
                acc.z = fmaf(c, v.z, acc.z);
                acc.w = fmaf(c, v.w, acc.w);
            }
        }
        __syncthreads();
    }
    if (t < HRD / 4)
        reinterpret_cast<float4*>(g_gembp + (size_t)blockIdx.x * HRD)[t] = acc;
}

__global__ void final_kernel(const float* __restrict__ pi,
                             const float* __restrict__ pi_w,
                             const float* __restrict__ pi_b,
                             const float* __restrict__ out_w,
                             const float* __restrict__ out_b,
                             float* __restrict__ out) {
    __shared__ float pie[16];
    int b = blockIdx.x, tid = threadIdx.x;
    if (tid < 16) {
        float a = pi_b[tid];
#pragma unroll
        for (int k = 0; k < 25; k++) a = fmaf(pi[b * 25 + k], pi_w[k * 16 + tid], a);
        pie[tid] = fmaxf(a, 0.f);
    }
    __syncthreads();
    int o = tid >> 5, lane = tid & 31;
    float acc = 0.f;
    const float* g0 = g_gembp + (size_t)(b * 4 + 0) * HRD;
    const float* g1 = g_gembp + (size_t)(b * 4 + 1) * HRD;
    const float* g2 = g_gembp + (size_t)(b * 4 + 2) * HRD;
    const float* g3 = g_gembp + (size_t)(b * 4 + 3) * HRD;
    for (int j = lane; j < HRD; j += 32) {
        float ge = (g0[j] + g1[j]) + (g2[j] + g3[j]);
        acc = fmaf(ge, out_w[j * NOUT + o], acc);
    }
    if (lane < 16) acc = fmaf(pie[lane], out_w[(HRD + lane) * NOUT + o], acc);
#pragma unroll
    for (int off = 16; off; off >>= 1) acc += __shfl_down_sync(0xffffffffu, acc, off);
    if (lane == 0) out[b * NOUT + o] = acc + out_b[o];
}

// ---------------- launch -----------------------------------------------------
extern "C" void kernel_launch(void* const* d_in, const int* in_sizes, int n_in,
                              void* d_out, int out_size) {
    const float* x    = (const float*)d_in[0];
    const float* pi   = (const float*)d_in[1];
    const float* eps  = (const float*)d_in[2];
    const float* w1   = (const float*)d_in[3];
    const float* b1   = (const float*)d_in[4];
    const float* bng1 = (const float*)d_in[5];
    const float* bnb1 = (const float*)d_in[6];
    const float* w2   = (const float*)d_in[7];
    const float* b2   = (const float*)d_in[8];
    const float* bng  = (const float*)d_in[9];
    const float* bnb  = (const float*)d_in[10];
    const float* aw   = (const float*)d_in[11];
    const float* ab   = (const float*)d_in[12];
    const float* pw   = (const float*)d_in[13];
    const float* pb   = (const float*)d_in[14];
    const float* ow   = (const float*)d_in[15];
    const float* ob   = (const float*)d_in[16];
    const int*   ei   = (const int*)d_in[17];
    const int*   gid  = (const int*)d_in[18];
    const int* src = ei;
    const int* dst = ei + EE;
    float* out = (float*)d_out;

    cudaFuncSetAttribute(gemm128_kernel<true>,
                         cudaFuncAttributeMaxDynamicSharedMemorySize, GEMM_SMEM);
    cudaFuncSetAttribute(gemm128_kernel<false>,
                         cudaFuncAttributeMaxDynamicSharedMemorySize, GEMM_SMEM);

    const int ELT_BLOCKS = (NN * 32 + 255) / 256;          // 6250
    const int GEMM_BLOCKS = (NN + TILE_R - 1) / TILE_R;    // 285
    const int EDGE_BLK = (EE + 255) / 256;                 // 3125

    // ---- CSR by dst; g_cnt==0 at entry, scan re-zeroes it and seeds g_cur ----
    hist_kernel<<<EDGE_BLK, 256>>>(dst);                   // launch 1
    scan_kernel<<<1, 1024>>>();                            // launch 2
    scatter_kernel<<<EDGE_BLK, 256>>>(src, dst);           // launch 3

    for (int l = 0; l < LL; l++) {
        gemm128_kernel<true><<<GEMM_BLOCKS, 256, GEMM_SMEM>>>(   // launch 4 = l0 (profiled)
            w1 + (size_t)l * DD * DD, b1 + l * DD, x, eps, l);
        if (l == 0) copyx_scores_kernel<<<ELT_BLOCKS, 256>>>(x, aw, ab);
        finalize_bn_kernel<<<1, DD>>>(bng1 + l * DD, bnb1 + l * DD);
        gemm128_kernel<false><<<GEMM_BLOCKS, 256, GEMM_SMEM>>>(
            w2 + (size_t)l * DD * DD, b2 + l * DD, x, eps, l);
        finalize_bn_kernel<<<1, DD>>>(bng + l * DD, bnb + l * DD);
        apply_h_kernel<<<ELT_BLOCKS, 256>>>(l, aw);
    }

    gemb_part_kernel<<<4 * BB, 256>>>(gid);
    final_kernel<<<BB, 320>>>(pi, pw, pb, ow, ob, out);
}